// round 13
// baseline (speedup 1.0000x reference)
#include <cuda_runtime.h>
#include <stdint.h>

#define NB   64
#define CIN  96
#define HWp  784
#define CMID 576
#define NPIX (NB*HWp)          // 50176
#define KW1  24                // 96/4
#define KW3  144               // 576/4
#define OUT_ELEMS (NB*CIN*HWp) // 4816896

// ---------------- device scratch ----------------
__device__ float    g_s[4];
__device__ uint32_t g_xq [NPIX*KW1];
__device__ uint32_t g_y2q[NPIX*KW3];
__device__ uint32_t g_w1q[CMID*KW1];
__device__ uint32_t g_w2q[CMID*3];     // per channel: 3 row-words (k0,k1,k2,0)
__device__ uint32_t g_w3q[CIN*KW3];
__device__ float g_a1[CMID], g_bb1[CMID];
__device__ float g_a2[CMID], g_bb2[CMID];
__device__ float g_a3[CIN],  g_bb3[CIN];

__device__ __forceinline__ float clampf(float v, float lo, float hi){ return fminf(fmaxf(v,lo),hi); }

__device__ __forceinline__ void imma(int& d0,int& d1,int& d2,int& d3,
                                     uint32_t a0,uint32_t a1,uint32_t a2,uint32_t a3,
                                     uint32_t b0,uint32_t b1){
    asm volatile("mma.sync.aligned.m16n8k32.row.col.s32.s8.s8.s32 "
                 "{%0,%1,%2,%3},{%4,%5,%6,%7},{%8,%9},{%0,%1,%2,%3};"
                 : "+r"(d0),"+r"(d1),"+r"(d2),"+r"(d3)
                 : "r"(a0),"r"(a1),"r"(a2),"r"(a3),"r"(b0),"r"(b1));
}
__device__ __forceinline__ void ldm_x4(uint32_t& r0,uint32_t& r1,uint32_t& r2,uint32_t& r3,
                                       uint32_t addr){
    asm volatile("ldmatrix.sync.aligned.m8n8.x4.shared.b16 {%0,%1,%2,%3}, [%4];"
                 : "=r"(r0),"=r"(r1),"=r"(r2),"=r"(r3) : "r"(addr));
}
__device__ __forceinline__ void cpa16(uint32_t dst, const void* src){
    asm volatile("cp.async.cg.shared.global [%0], [%1], 16;" :: "r"(dst), "l"(src));
}
__device__ __forceinline__ void cpa16z(uint32_t dst, const void* src, uint32_t nsrc){
    asm volatile("cp.async.cg.shared.global [%0], [%1], 16, %2;" :: "r"(dst), "l"(src), "r"(nsrc));
}
__device__ __forceinline__ void cp_commit_wait(){
    asm volatile("cp.async.commit_group;");
    asm volatile("cp.async.wait_group 0;");
}
__device__ __forceinline__ uint32_t smem_u32(const void* p){
    uint32_t a;
    asm("{ .reg .u64 t; cvta.to.shared.u64 t, %1; cvt.u32.u64 %0, t; }" : "=r"(a) : "l"(p));
    return a;
}

// ---------------- single prep kernel: 681 blocks ----------------
__global__ __launch_bounds__(192) void k_prep(
    const float* __restrict__ w1, const float* __restrict__ g1, const float* __restrict__ b1,
    const float* __restrict__ m1, const float* __restrict__ v1,
    const float* __restrict__ w2, const float* __restrict__ g2, const float* __restrict__ b2,
    const float* __restrict__ m2, const float* __restrict__ v2,
    const float* __restrict__ w3, const float* __restrict__ g3, const float* __restrict__ b3,
    const float* __restrict__ m3, const float* __restrict__ v3,
    const float* __restrict__ r0, const float* __restrict__ r1,
    const float* __restrict__ r2, const float* __restrict__ r3,
    const int* __restrict__ cl_)
{
    __shared__ float red[6];
    int bid = blockIdx.x, t = threadIdx.x;
    int cl = cl_[0];
    if (bid == 0 && t == 0){
        g_s[0]=r0[cl]/127.0f; g_s[1]=r1[cl]/127.0f;
        g_s[2]=r2[cl]/127.0f; g_s[3]=r3[cl]/127.0f;
    }
    if (bid < CMID){
        int o = bid;
        float sc = g1[o] * rsqrtf(v1[o] + 1e-5f);
        float wf = 0.f;
        if (t < 96) wf = w1[o*CIN + t] * sc;
        float amx = fabsf(wf);
        #pragma unroll
        for (int off=16; off; off>>=1) amx = fmaxf(amx, __shfl_xor_sync(0xffffffffu, amx, off));
        if ((t & 31) == 0) red[t>>5] = amx;
        __syncthreads();
        float mx = red[0];
        #pragma unroll
        for (int i=1;i<6;i++) mx = fmaxf(mx, red[i]);
        float sw = mx / 127.0f;
        if (t < 96){
            float q = clampf(rintf(wf / sw), -127.f, 127.f);
            ((int8_t*)g_w1q)[o*CIN + t] = (int8_t)q;
        }
        if (t == 0){
            float s0 = r0[cl]/127.0f;
            g_a1[o] = s0*sw; g_bb1[o] = b1[o] - m1[o]*sc;
        }
    } else if (bid < CMID + 9){
        if (t < 64){
            int c = (bid - CMID)*64 + t;
            float sc = g2[c] * rsqrtf(v2[c] + 1e-5f);
            float wf[9]; float mx = 0.f;
            #pragma unroll
            for (int j=0;j<9;j++){ wf[j] = w2[c*9+j]*sc; mx = fmaxf(mx, fabsf(wf[j])); }
            float sw = mx / 127.0f;
            #pragma unroll
            for (int dh=0; dh<3; dh++){
                uint32_t pk = 0;
                #pragma unroll
                for (int dw=0; dw<3; dw++){
                    int q = (int)clampf(rintf(wf[dh*3+dw]/sw), -127.f, 127.f);
                    pk |= ((uint32_t)(uint8_t)(int8_t)q) << (8*dw);
                }
                g_w2q[c*3 + dh] = pk;
            }
            float s1 = r1[cl]/127.0f;
            g_a2[c] = s1*sw; g_bb2[c] = b2[c] - m2[c]*sc;
        }
    } else {
        int o = bid - (CMID + 9);
        float sc = g3[o] * rsqrtf(v3[o] + 1e-5f);
        float f0 = w3[o*CMID + t      ]*sc;
        float f1 = w3[o*CMID + t + 192]*sc;
        float f2 = w3[o*CMID + t + 384]*sc;
        float amx = fmaxf(fabsf(f0), fmaxf(fabsf(f1), fabsf(f2)));
        #pragma unroll
        for (int off=16; off; off>>=1) amx = fmaxf(amx, __shfl_xor_sync(0xffffffffu, amx, off));
        if ((t & 31) == 0) red[t>>5] = amx;
        __syncthreads();
        float mx = red[0];
        #pragma unroll
        for (int i=1;i<6;i++) mx = fmaxf(mx, red[i]);
        float sw = mx / 127.0f;
        int8_t* dst = (int8_t*)g_w3q + o*CMID;
        dst[t      ] = (int8_t)clampf(rintf(f0/sw), -127.f, 127.f);
        dst[t + 192] = (int8_t)clampf(rintf(f1/sw), -127.f, 127.f);
        dst[t + 384] = (int8_t)clampf(rintf(f2/sw), -127.f, 127.f);
        if (t == 0){
            float s2 = r2[cl]/127.0f;
            g_a3[o] = s2*sw; g_bb3[o] = b3[o] - m3[o]*sc;
        }
    }
}

// ---------------- stage 0: quantize x ----------------
__global__ __launch_bounds__(128) void k_qx(const float* __restrict__ x){
    __shared__ int8_t sq[CIN*128];
    int t  = threadIdx.x;
    int p0 = blockIdx.x*128;
    int p  = p0 + t;
    int b  = p / HWp, hw = p % HWp;
    const float* xb = x + (size_t)b*CIN*HWp + hw;
    float inv0 = 1.0f / g_s[0];
    #pragma unroll 4
    for (int c=0;c<CIN;c++){
        float q = clampf(rintf(xb[(size_t)c*HWp] * inv0), -127.f, 127.f);
        sq[c*128 + t] = (int8_t)q;
    }
    __syncthreads();
    uint32_t* ow = g_xq + (size_t)p0*KW1;
    for (int w=t; w<128*KW1; w+=128){
        int pl = w / KW1;
        int c0 = (w % KW1)*4;
        uint32_t v =  (uint32_t)(uint8_t)sq[(c0+0)*128+pl]
                   | ((uint32_t)(uint8_t)sq[(c0+1)*128+pl] << 8)
                   | ((uint32_t)(uint8_t)sq[(c0+2)*128+pl] << 16)
                   | ((uint32_t)(uint8_t)sq[(c0+3)*128+pl] << 24);
        ow[w] = v;
    }
}

// ---------------- fused conv1 + depthwise, half-image slabs, hoisted B frags ----------------
// block = (ch chunk 0..8, img, half 0..1). Slab = 16 rows (1 halo each side) x 28 = 448 px.
#define SAW  28            // A/W smem pitch (words) = 112 B
#define SPX  448
#define Y1S  113           // y1 stride per channel (words); 452 bytes
#define D_OFF_W  (SPX*SAW)                 // 12544
#define D_OFF_Y1 (D_OFF_W + 64*SAW)        // 14336
#define D_OFF_SC (D_OFF_Y1 + 64*Y1S)       // 21568
#define D_WORDS  (D_OFF_SC + 128)          // 21696
#define D_BYTES  (D_WORDS*4)               // 86784
__global__ __launch_bounds__(256,2) void k_c1dw(){
    extern __shared__ __align__(16) uint32_t sm[];
    uint32_t* y1 = sm + D_OFF_Y1;
    float* sAf = (float*)(sm + D_OFF_SC);
    float* sBf = (float*)(sm + D_OFF_SC + 64);
    int t    = threadIdx.x;
    int ch   = blockIdx.x;
    int img  = blockIdx.y;
    int half = blockIdx.z;
    int off  = half*392 - 28;       // slab px -> image px offset
    uint32_t sbase = smem_u32(sm);

    if (t < 64){ sAf[t] = g_a1[ch*64+t]; sBf[t] = g_bb1[ch*64+t]; }
    const uint32_t* Aim = g_xq + (size_t)img*HWp*KW1;
    for (int i=t; i<SPX*6; i+=256){
        int sp = i/6, q = i%6;
        int ip = sp + off;
        uint32_t v = ((unsigned)ip < (unsigned)HWp) ? 16u : 0u;
        cpa16z(sbase + (uint32_t)(sp*SAW + q*4)*4, &Aim[(v? ip:0)*KW1 + q*4], v);
    }
    for (int i=t; i<64*6; i+=256){
        int r = i/6, q = i%6;
        cpa16(sbase + (uint32_t)(D_OFF_W + r*SAW + q*4)*4, &g_w1q[(ch*64+r)*KW1 + q*4]);
    }
    cp_commit_wait();
    __syncthreads();

    int lane = t & 31, warp = t >> 5, r4 = lane >> 2, w4 = lane & 3;
    float inv1 = 1.0f / g_s[1];
    int8_t* y1b = (int8_t*)y1;
    uint32_t aLane = sbase + ((lane&7) + ((lane>>3)&1)*8)*112 + ((lane>>4)&1)*16;
    uint32_t bLane = sbase + (uint32_t)D_OFF_W*4
                   + ((lane&7) + ((lane>>4)&1)*8)*112 + ((lane>>3)&1)*16;

    // hoist ALL B fragments: 3 kc x 4 n-tiles x ldmatrix.x4 = 48 regs, 12 LDSM total
    uint32_t bf[3][4][4];
    #pragma unroll
    for (int kc=0;kc<3;kc++)
        #pragma unroll
        for (int nt=0;nt<4;nt++)
            ldm_x4(bf[kc][nt][0],bf[kc][nt][1],bf[kc][nt][2],bf[kc][nt][3],
                   bLane + (uint32_t)(nt*16*112 + kc*32));

    for (int tile = warp; tile < 28; tile += 8){
        int m0 = tile*16;
        int acc[8][4] = {};
        uint32_t a[2][4];
        ldm_x4(a[0][0],a[0][1],a[0][2],a[0][3], aLane + (uint32_t)(m0*112));
        #pragma unroll
        for (int kc=0;kc<3;kc++){
            const int cur = kc & 1, nxt = cur ^ 1;
            if (kc < 2)
                ldm_x4(a[nxt][0],a[nxt][1],a[nxt][2],a[nxt][3],
                       aLane + (uint32_t)(m0*112 + (kc+1)*32));
            #pragma unroll
            for (int nt=0;nt<4;nt++){
                imma(acc[2*nt  ][0],acc[2*nt  ][1],acc[2*nt  ][2],acc[2*nt  ][3],
                     a[cur][0],a[cur][1],a[cur][2],a[cur][3], bf[kc][nt][0], bf[kc][nt][1]);
                imma(acc[2*nt+1][0],acc[2*nt+1][1],acc[2*nt+1][2],acc[2*nt+1][3],
                     a[cur][0],a[cur][1],a[cur][2],a[cur][3], bf[kc][nt][2], bf[kc][nt][3]);
            }
        }
        int px0 = m0 + r4, px1 = px0 + 8;
        bool v0 = (unsigned)(px0 + off) < (unsigned)HWp;
        bool v1 = (unsigned)(px1 + off) < (unsigned)HWp;
        #pragma unroll
        for (int ni=0;ni<8;ni++){
            int c0 = ni*8 + 2*w4;
            float af0 = sAf[c0], af1 = sAf[c0+1];
            float bb0 = sBf[c0], bb1 = sBf[c0+1];
            float q0 = fminf(rintf(clampf(fmaf(af0,(float)acc[ni][0],bb0),0.f,6.f)*inv1),127.f);
            float q1 = fminf(rintf(clampf(fmaf(af1,(float)acc[ni][1],bb1),0.f,6.f)*inv1),127.f);
            float q2 = fminf(rintf(clampf(fmaf(af0,(float)acc[ni][2],bb0),0.f,6.f)*inv1),127.f);
            float q3 = fminf(rintf(clampf(fmaf(af1,(float)acc[ni][3],bb1),0.f,6.f)*inv1),127.f);
            y1b[ c0   *452 + px0] = v0 ? (int8_t)(int)q0 : (int8_t)0;
            y1b[(c0+1)*452 + px0] = v0 ? (int8_t)(int)q1 : (int8_t)0;
            y1b[ c0   *452 + px1] = v1 ? (int8_t)(int)q2 : (int8_t)0;
            y1b[(c0+1)*452 + px1] = v1 ? (int8_t)(int)q3 : (int8_t)0;
        }
    }
    __syncthreads();

    // depthwise: output rows j=0..13 use y1 slab rows j, j+1, j+2
    float inv2 = 1.0f / g_s[2];
    int8_t* y2b = (int8_t*)sm;     // alias over A region (free after MMA)
    for (int task=t; task<64*14; task+=256){
        int c = task & 63, j = task >> 6;
        int cg = ch*64 + c;
        uint32_t wk0 = g_w2q[cg*3+0], wk1 = g_w2q[cg*3+1], wk2 = g_w2q[cg*3+2];
        float a2 = g_a2[cg], b2 = g_bb2[cg];
        const uint32_t* rw = y1 + c*Y1S;
        uint32_t rm[7], rc[7], rp[7];
        #pragma unroll
        for (int q=0;q<7;q++){
            rm[q] = rw[ j   *7 + q];
            rc[q] = rw[(j+1)*7 + q];
            rp[q] = rw[(j+2)*7 + q];
        }
        uint32_t pm=0, pc=0, pp=0;
        #pragma unroll
        for (int w=0; w<7; w++){
            uint32_t nm = (w<6)? rm[w+1] : 0u;
            uint32_t nc = (w<6)? rc[w+1] : 0u;
            uint32_t np = (w<6)? rp[w+1] : 0u;
            int o0 = __dp4a((int)__byte_perm(pm, rm[w], 0x6543), (int)wk0, 0)
                   + __dp4a((int)__byte_perm(pc, rc[w], 0x6543), (int)wk1, 0)
                   + __dp4a((int)__byte_perm(pp, rp[w], 0x6543), (int)wk2, 0);
            int o1 = __dp4a((int)rm[w], (int)wk0, 0)
                   + __dp4a((int)rc[w], (int)wk1, 0)
                   + __dp4a((int)rp[w], (int)wk2, 0);
            int o2 = __dp4a((int)__byte_perm(rm[w], nm, 0x4321), (int)wk0, 0)
                   + __dp4a((int)__byte_perm(rc[w], nc, 0x4321), (int)wk1, 0)
                   + __dp4a((int)__byte_perm(rp[w], np, 0x4321), (int)wk2, 0);
            int o3 = __dp4a((int)__byte_perm(rm[w], nm, 0x5432), (int)wk0, 0)
                   + __dp4a((int)__byte_perm(rc[w], nc, 0x5432), (int)wk1, 0)
                   + __dp4a((int)__byte_perm(rp[w], np, 0x5432), (int)wk2, 0);
            int outs[4] = {o0, o1, o2, o3};
            #pragma unroll
            for (int i2=0;i2<4;i2++){
                float y = clampf(fmaf(a2, (float)outs[i2], b2), 0.f, 6.f);
                int q = (int)fminf(rintf(y*inv2), 127.f);
                y2b[(j*28 + w*4 + i2)*64 + c] = (int8_t)q;
            }
            pm = rm[w]; pc = rc[w]; pp = rp[w];
        }
    }
    __syncthreads();

    uint32_t* dst = g_y2q + ((size_t)img*HWp + half*392)*KW3 + ch*16;
    const uint32_t* y2w = sm;
    for (int i=t; i<392*4; i+=256){
        int p = i>>2, q = i&3;
        *(uint4*)&dst[(size_t)p*KW3 + q*4] = *(const uint4*)&y2w[p*16 + q*4];
    }
}

// ---------------- conv3: 64px x 96ch, 256 thr, 2 CTA/SM, pipelined ----------------
#define SB3 148
#define C3B  192                      // after 192 words of scale cache
#define C3A  (C3B + CIN*SB3)          // 192 + 14208 = 14400
#define C3_WORDS (C3A + 64*SB3)       // + 9472 = 23872
#define C3_BYTES (C3_WORDS*4)         // 95488
#define SO3 101
__global__ __launch_bounds__(256,2) void k_conv3(const float* __restrict__ x,
                                                 float* __restrict__ out, int out_size){
    extern __shared__ __align__(16) uint32_t sm[];
    float* sa3 = (float*)sm;          // 96
    float* sb3 = (float*)(sm + 96);   // 96
    int t = threadIdx.x;
    int p0 = blockIdx.x*64;
    uint32_t sbase = smem_u32(sm);

    if (t < 96){ sa3[t] = g_a3[t]; sb3[t] = g_bb3[t]; }
    for (int i=t; i<CIN*36; i+=256){
        int r = i/36, q = i%36;
        cpa16(sbase + (uint32_t)(C3B + r*SB3 + q*4)*4, &g_w3q[r*KW3 + q*4]);
    }
    const uint32_t* Ag = g_y2q + (size_t)p0*KW3;
    for (int i=t; i<64*36; i+=256){
        int r = i/36, q = i%36;
        cpa16(sbase + (uint32_t)(C3A + r*SB3 + q*4)*4, &Ag[r*KW3 + q*4]);
    }
    cp_commit_wait();
    __syncthreads();

    int lane = t & 31, warp = t >> 5, r4 = lane >> 2, w4 = lane & 3;
    int m0 = (warp & 3)*16, n0 = (warp >> 2)*48;
    uint32_t aBase = sbase + (uint32_t)C3A*4
                   + (uint32_t)(m0 + (lane&7) + ((lane>>3)&1)*8)*592 + ((lane>>4)&1)*16;
    uint32_t bBase = sbase + (uint32_t)C3B*4
                   + (uint32_t)(n0 + (lane&7) + ((lane>>4)&1)*8)*592 + ((lane>>3)&1)*16;
    int acc[6][4] = {};
    uint32_t a[2][4], b[2][3][4];
    ldm_x4(a[0][0],a[0][1],a[0][2],a[0][3], aBase);
    #pragma unroll
    for (int tp=0; tp<3; tp++)
        ldm_x4(b[0][tp][0],b[0][tp][1],b[0][tp][2],b[0][tp][3],
               bBase + (uint32_t)(tp*16*592));
    #pragma unroll
    for (int ks=0; ks<18; ks++){
        const int cur = ks & 1, nxt = cur ^ 1;
        if (ks < 17){
            ldm_x4(a[nxt][0],a[nxt][1],a[nxt][2],a[nxt][3], aBase + (uint32_t)((ks+1)*32));
            #pragma unroll
            for (int tp=0; tp<3; tp++)
                ldm_x4(b[nxt][tp][0],b[nxt][tp][1],b[nxt][tp][2],b[nxt][tp][3],
                       bBase + (uint32_t)(tp*16*592 + (ks+1)*32));
        }
        #pragma unroll
        for (int tp=0; tp<3; tp++){
            imma(acc[2*tp  ][0],acc[2*tp  ][1],acc[2*tp  ][2],acc[2*tp  ][3],
                 a[cur][0],a[cur][1],a[cur][2],a[cur][3], b[cur][tp][0], b[cur][tp][1]);
            imma(acc[2*tp+1][0],acc[2*tp+1][1],acc[2*tp+1][2],acc[2*tp+1][3],
                 a[cur][0],a[cur][1],a[cur][2],a[cur][3], b[cur][tp][2], b[cur][tp][3]);
        }
    }
    __syncthreads();
    float* sO = (float*)(sm + C3A);   // 64 x 101 floats, over A region
    #pragma unroll
    for (int ni=0; ni<6; ni++){
        int c = n0 + ni*8 + 2*w4;
        float af0 = sa3[c],  af1 = sa3[c+1];
        float bf0 = sb3[c],  bf1 = sb3[c+1];
        int row0 = m0 + r4;
        sO[ row0   *SO3 + c    ] = fmaf(af0, (float)acc[ni][0], bf0);
        sO[ row0   *SO3 + c + 1] = fmaf(af1, (float)acc[ni][1], bf1);
        sO[(row0+8)*SO3 + c    ] = fmaf(af0, (float)acc[ni][2], bf0);
        sO[(row0+8)*SO3 + c + 1] = fmaf(af1, (float)acc[ni][3], bf1);
    }
    __syncthreads();
    float s3 = g_s[3];
    float inv3 = 1.0f / s3;
    for (int idx=t; idx<CIN*64; idx+=256){
        int c = idx >> 6, pl = idx & 63;
        int p = p0 + pl;
        int b2 = p / HWp, hw = p % HWp;
        size_t g = (size_t)b2*CIN*HWp + (size_t)c*HWp + hw;
        float y = sO[pl*SO3 + c] + x[g];
        float q = clampf(rintf(y*inv3), -127.f, 127.f);
        out[g] = q * s3;
    }
    if (blockIdx.x == 0){
        for (int i = OUT_ELEMS + t; i < out_size; i += 256) out[i] = g_s[3];
    }
}

// ---------------- launch ----------------
extern "C" void kernel_launch(void* const* d_in, const int* in_sizes, int n_in,
                              void* d_out, int out_size){
    const float* x  = (const float*)d_in[0];
    const float* w1 = (const float*)d_in[1];
    const float* g1 = (const float*)d_in[2];
    const float* b1 = (const float*)d_in[3];
    const float* m1 = (const float*)d_in[4];
    const float* v1 = (const float*)d_in[5];
    const float* w2 = (const float*)d_in[6];
    const float* g2 = (const float*)d_in[7];
    const float* b2 = (const float*)d_in[8];
    const float* m2 = (const float*)d_in[9];
    const float* v2 = (const float*)d_in[10];
    const float* w3 = (const float*)d_in[11];
    const float* g3 = (const float*)d_in[12];
    const float* b3 = (const float*)d_in[13];
    const float* m3 = (const float*)d_in[14];
    const float* v3 = (const float*)d_in[15];
    const float* r0 = (const float*)d_in[16];
    const float* r1 = (const float*)d_in[17];
    const float* r2 = (const float*)d_in[18];
    const float* r3 = (const float*)d_in[19];
    const int*   cl = (const int*)d_in[20];

    cudaFuncSetAttribute(k_c1dw,  cudaFuncAttributeMaxDynamicSharedMemorySize, D_BYTES);
    cudaFuncSetAttribute(k_conv3, cudaFuncAttributeMaxDynamicSharedMemorySize, C3_BYTES);

    k_prep<<<CMID + 9 + CIN, 192>>>(w1,g1,b1,m1,v1, w2,g2,b2,m2,v2, w3,g3,b3,m3,v3,
                                    r0,r1,r2,r3, cl);
    k_qx<<<NPIX/128, 128>>>(x);
    k_c1dw<<<dim3(9, NB, 2), 256, D_BYTES>>>();
    k_conv3<<<NPIX/64, 256, C3_BYTES>>>(x, (float*)d_out, out_size);
}

// round 15
// speedup vs baseline: 1.0332x; 1.0332x over previous
#include <cuda_runtime.h>
#include <stdint.h>

#define NB   64
#define CIN  96
#define HWp  784
#define CMID 576
#define NPIX (NB*HWp)          // 50176
#define KW1  24                // 96/4
#define KW3  144               // 576/4
#define OUT_ELEMS (NB*CIN*HWp) // 4816896

// ---------------- device scratch ----------------
__device__ float    g_s[4];
__device__ uint32_t g_xq [NPIX*KW1];
__device__ uint32_t g_y2q[NPIX*KW3];
__device__ uint32_t g_w1q[CMID*KW1];
__device__ uint32_t g_w2q[CMID*3];     // per channel: 3 row-words (k0,k1,k2,0)
__device__ uint32_t g_w3q[CIN*KW3];
__device__ float g_a1[CMID], g_bb1[CMID];
__device__ float g_a2[CMID], g_bb2[CMID];
__device__ float g_a3[CIN],  g_bb3[CIN];

__device__ __forceinline__ float clampf(float v, float lo, float hi){ return fminf(fmaxf(v,lo),hi); }

__device__ __forceinline__ void imma(int& d0,int& d1,int& d2,int& d3,
                                     uint32_t a0,uint32_t a1,uint32_t a2,uint32_t a3,
                                     uint32_t b0,uint32_t b1){
    asm volatile("mma.sync.aligned.m16n8k32.row.col.s32.s8.s8.s32 "
                 "{%0,%1,%2,%3},{%4,%5,%6,%7},{%8,%9},{%0,%1,%2,%3};"
                 : "+r"(d0),"+r"(d1),"+r"(d2),"+r"(d3)
                 : "r"(a0),"r"(a1),"r"(a2),"r"(a3),"r"(b0),"r"(b1));
}
__device__ __forceinline__ void ldm_x4(uint32_t& r0,uint32_t& r1,uint32_t& r2,uint32_t& r3,
                                       uint32_t addr){
    asm volatile("ldmatrix.sync.aligned.m8n8.x4.shared.b16 {%0,%1,%2,%3}, [%4];"
                 : "=r"(r0),"=r"(r1),"=r"(r2),"=r"(r3) : "r"(addr));
}
__device__ __forceinline__ void ldm_x2(uint32_t& r0,uint32_t& r1, uint32_t addr){
    asm volatile("ldmatrix.sync.aligned.m8n8.x2.shared.b16 {%0,%1}, [%2];"
                 : "=r"(r0),"=r"(r1) : "r"(addr));
}
__device__ __forceinline__ void cpa16(uint32_t dst, const void* src){
    asm volatile("cp.async.cg.shared.global [%0], [%1], 16;" :: "r"(dst), "l"(src));
}
__device__ __forceinline__ void cpa16z(uint32_t dst, const void* src, uint32_t nsrc){
    asm volatile("cp.async.cg.shared.global [%0], [%1], 16, %2;" :: "r"(dst), "l"(src), "r"(nsrc));
}
__device__ __forceinline__ void cp_commit_wait(){
    asm volatile("cp.async.commit_group;");
    asm volatile("cp.async.wait_group 0;");
}
__device__ __forceinline__ uint32_t smem_u32(const void* p){
    uint32_t a;
    asm("{ .reg .u64 t; cvta.to.shared.u64 t, %1; cvt.u32.u64 %0, t; }" : "=r"(a) : "l"(p));
    return a;
}

// ---------------- merged prep + qx kernel ----------------
// blocks [0,576):        conv1 weight row o=bid
// blocks [576,585):      depthwise weights, 64 ch/block
// blocks [585,681):      conv3 weight row o=bid-585
// blocks [681,681+392):  quantize-x chunk of 128 pixels
#define NPREP (CMID + 9 + CIN)      // 681
__global__ __launch_bounds__(192) void k_prepqx(
    const float* __restrict__ x,
    const float* __restrict__ w1, const float* __restrict__ g1, const float* __restrict__ b1,
    const float* __restrict__ m1, const float* __restrict__ v1,
    const float* __restrict__ w2, const float* __restrict__ g2, const float* __restrict__ b2,
    const float* __restrict__ m2, const float* __restrict__ v2,
    const float* __restrict__ w3, const float* __restrict__ g3, const float* __restrict__ b3,
    const float* __restrict__ m3, const float* __restrict__ v3,
    const float* __restrict__ r0, const float* __restrict__ r1,
    const float* __restrict__ r2, const float* __restrict__ r3,
    const int* __restrict__ cl_)
{
    __shared__ __align__(16) int8_t sq[CIN*128];   // 12 KB (qx path); prep uses first 24B as float red[6]
    float* red = (float*)sq;
    int bid = blockIdx.x, t = threadIdx.x;
    int cl = cl_[0];
    if (bid == 0 && t == 0){
        g_s[0]=r0[cl]/127.0f; g_s[1]=r1[cl]/127.0f;
        g_s[2]=r2[cl]/127.0f; g_s[3]=r3[cl]/127.0f;
    }
    if (bid < CMID){
        int o = bid;
        float sc = g1[o] * rsqrtf(v1[o] + 1e-5f);
        float wf = 0.f;
        if (t < 96) wf = w1[o*CIN + t] * sc;
        float amx = fabsf(wf);
        #pragma unroll
        for (int off=16; off; off>>=1) amx = fmaxf(amx, __shfl_xor_sync(0xffffffffu, amx, off));
        if ((t & 31) == 0) red[t>>5] = amx;
        __syncthreads();
        float mx = red[0];
        #pragma unroll
        for (int i=1;i<6;i++) mx = fmaxf(mx, red[i]);
        float sw = mx / 127.0f;
        if (t < 96){
            float q = clampf(rintf(wf / sw), -127.f, 127.f);
            ((int8_t*)g_w1q)[o*CIN + t] = (int8_t)q;
        }
        if (t == 0){
            float s0 = r0[cl]/127.0f;
            g_a1[o] = s0*sw; g_bb1[o] = b1[o] - m1[o]*sc;
        }
    } else if (bid < CMID + 9){
        if (t < 64){
            int c = (bid - CMID)*64 + t;
            float sc = g2[c] * rsqrtf(v2[c] + 1e-5f);
            float wf[9]; float mx = 0.f;
            #pragma unroll
            for (int j=0;j<9;j++){ wf[j] = w2[c*9+j]*sc; mx = fmaxf(mx, fabsf(wf[j])); }
            float sw = mx / 127.0f;
            #pragma unroll
            for (int dh=0; dh<3; dh++){
                uint32_t pk = 0;
                #pragma unroll
                for (int dw=0; dw<3; dw++){
                    int q = (int)clampf(rintf(wf[dh*3+dw]/sw), -127.f, 127.f);
                    pk |= ((uint32_t)(uint8_t)(int8_t)q) << (8*dw);
                }
                g_w2q[c*3 + dh] = pk;
            }
            float s1 = r1[cl]/127.0f;
            g_a2[c] = s1*sw; g_bb2[c] = b2[c] - m2[c]*sc;
        }
    } else if (bid < NPREP){
        int o = bid - (CMID + 9);
        float sc = g3[o] * rsqrtf(v3[o] + 1e-5f);
        float f0 = w3[o*CMID + t      ]*sc;
        float f1 = w3[o*CMID + t + 192]*sc;
        float f2 = w3[o*CMID + t + 384]*sc;
        float amx = fmaxf(fabsf(f0), fmaxf(fabsf(f1), fabsf(f2)));
        #pragma unroll
        for (int off=16; off; off>>=1) amx = fmaxf(amx, __shfl_xor_sync(0xffffffffu, amx, off));
        if ((t & 31) == 0) red[t>>5] = amx;
        __syncthreads();
        float mx = red[0];
        #pragma unroll
        for (int i=1;i<6;i++) mx = fmaxf(mx, red[i]);
        float sw = mx / 127.0f;
        int8_t* dst = (int8_t*)g_w3q + o*CMID;
        dst[t      ] = (int8_t)clampf(rintf(f0/sw), -127.f, 127.f);
        dst[t + 192] = (int8_t)clampf(rintf(f1/sw), -127.f, 127.f);
        dst[t + 384] = (int8_t)clampf(rintf(f2/sw), -127.f, 127.f);
        if (t == 0){
            float s2 = r2[cl]/127.0f;
            g_a3[o] = s2*sw; g_bb3[o] = b3[o] - m3[o]*sc;
        }
    } else {
        // quantize-x part: independent of prep outputs (s0 computed locally)
        int p0 = (bid - NPREP)*128;
        float inv0 = 127.0f / r0[cl];
        if (t < 128){
            int p  = p0 + t;
            int b  = p / HWp, hw = p % HWp;
            const float* xb = x + (size_t)b*CIN*HWp + hw;
            #pragma unroll 4
            for (int c=0;c<CIN;c++){
                float q = clampf(rintf(xb[(size_t)c*HWp] * inv0), -127.f, 127.f);
                sq[c*128 + t] = (int8_t)q;
            }
        }
        __syncthreads();
        uint32_t* ow = g_xq + (size_t)p0*KW1;
        for (int w=t; w<128*KW1; w+=192){
            int pl = w / KW1;
            int c0 = (w % KW1)*4;
            uint32_t v =  (uint32_t)(uint8_t)sq[(c0+0)*128+pl]
                       | ((uint32_t)(uint8_t)sq[(c0+1)*128+pl] << 8)
                       | ((uint32_t)(uint8_t)sq[(c0+2)*128+pl] << 16)
                       | ((uint32_t)(uint8_t)sq[(c0+3)*128+pl] << 24);
            ow[w] = v;
        }
    }
}

// ---------------- fused conv1 + depthwise, quarter-image slabs, 3 CTA/SM ----------------
// (R11 variant — measured fastest)
#define SAW  28            // A/W smem pitch (words) = 112 B
#define SPX  256           // padded slab px (252 data)
#define Y1S  65            // y1 per-channel stride (words); 63 data words
#define D_OFF_W  (SPX*SAW)                 // 7168
#define D_OFF_Y1 (D_OFF_W + 64*SAW)        // 8960
#define D_OFF_SC (D_OFF_Y1 + 64*Y1S)       // 13120
#define D_WORDS  (D_OFF_SC + 128)          // 13248
#define D_BYTES  (D_WORDS*4)               // 52992
__global__ __launch_bounds__(256,3) void k_c1dw(){
    extern __shared__ __align__(16) uint32_t sm[];
    uint32_t* y1 = sm + D_OFF_Y1;
    float* sAf = (float*)(sm + D_OFF_SC);
    float* sBf = (float*)(sm + D_OFF_SC + 64);
    int t    = threadIdx.x;
    int ch   = blockIdx.x;
    int img  = blockIdx.y;
    int qtr  = blockIdx.z;
    int off  = qtr*196 - 28;       // slab px -> image px offset
    uint32_t sbase = smem_u32(sm);

    if (t < 64){ sAf[t] = g_a1[ch*64+t]; sBf[t] = g_bb1[ch*64+t]; }
    const uint32_t* Aim = g_xq + (size_t)img*HWp*KW1;
    for (int i=t; i<SPX*6; i+=256){
        int sp = i/6, q = i%6;
        int ip = sp + off;
        uint32_t v = (sp < 252 && (unsigned)ip < (unsigned)HWp) ? 16u : 0u;
        cpa16z(sbase + (uint32_t)(sp*SAW + q*4)*4, &Aim[(v? ip:0)*KW1 + q*4], v);
    }
    for (int i=t; i<64*6; i+=256){
        int r = i/6, q = i%6;
        cpa16(sbase + (uint32_t)(D_OFF_W + r*SAW + q*4)*4, &g_w1q[(ch*64+r)*KW1 + q*4]);
    }
    cp_commit_wait();
    __syncthreads();

    int lane = t & 31, warp = t >> 5, r4 = lane >> 2, w4 = lane & 3;
    float inv1 = 1.0f / g_s[1];
    int8_t* y1b = (int8_t*)y1;
    uint32_t aLane = sbase + ((lane&7) + ((lane>>3)&1)*8)*112 + ((lane>>4)&1)*16;
    uint32_t bLane = sbase + (uint32_t)D_OFF_W*4
                   + ((lane&7) + ((lane>>4)&1)*8)*112 + ((lane>>3)&1)*16;

    #pragma unroll
    for (int tile = warp; tile < 16; tile += 8){
        int m0 = tile*16;
        int acc[8][4] = {};
        #pragma unroll
        for (int kc=0;kc<3;kc++){
            uint32_t a0,a1,a2,a3;
            ldm_x4(a0,a1,a2,a3, aLane + (uint32_t)(m0*112 + kc*32));
            #pragma unroll
            for (int tp=0; tp<4; tp++){
                uint32_t b0,b1,b2,b3;
                ldm_x4(b0,b1,b2,b3, bLane + (uint32_t)(tp*16*112 + kc*32));
                imma(acc[2*tp  ][0],acc[2*tp  ][1],acc[2*tp  ][2],acc[2*tp  ][3],
                     a0,a1,a2,a3, b0,b1);
                imma(acc[2*tp+1][0],acc[2*tp+1][1],acc[2*tp+1][2],acc[2*tp+1][3],
                     a0,a1,a2,a3, b2,b3);
            }
        }
        int px0 = m0 + r4, px1 = px0 + 8;
        bool s0ok = px0 < 252, s1ok = px1 < 252;
        bool v0 = s0ok && (unsigned)(px0 + off) < (unsigned)HWp;
        bool v1 = s1ok && (unsigned)(px1 + off) < (unsigned)HWp;
        #pragma unroll
        for (int ni=0;ni<8;ni++){
            int c0 = ni*8 + 2*w4;
            float af0 = sAf[c0], af1 = sAf[c0+1];
            float bb0 = sBf[c0], bb1 = sBf[c0+1];
            float q0 = fminf(rintf(clampf(fmaf(af0,(float)acc[ni][0],bb0),0.f,6.f)*inv1),127.f);
            float q1 = fminf(rintf(clampf(fmaf(af1,(float)acc[ni][1],bb1),0.f,6.f)*inv1),127.f);
            float q2 = fminf(rintf(clampf(fmaf(af0,(float)acc[ni][2],bb0),0.f,6.f)*inv1),127.f);
            float q3 = fminf(rintf(clampf(fmaf(af1,(float)acc[ni][3],bb1),0.f,6.f)*inv1),127.f);
            if (s0ok){
                y1b[ c0   *260 + px0] = v0 ? (int8_t)(int)q0 : (int8_t)0;
                y1b[(c0+1)*260 + px0] = v0 ? (int8_t)(int)q1 : (int8_t)0;
            }
            if (s1ok){
                y1b[ c0   *260 + px1] = v1 ? (int8_t)(int)q2 : (int8_t)0;
                y1b[(c0+1)*260 + px1] = v1 ? (int8_t)(int)q3 : (int8_t)0;
            }
        }
    }
    __syncthreads();

    // depthwise: output rows j=0..6 use y1 slab rows j, j+1, j+2
    float inv2 = 1.0f / g_s[2];
    int8_t* y2b = (int8_t*)sm;     // alias over A region (free after MMA)
    for (int task=t; task<64*7; task+=256){
        int c = task & 63, j = task >> 6;
        int cg = ch*64 + c;
        uint32_t wk0 = g_w2q[cg*3+0], wk1 = g_w2q[cg*3+1], wk2 = g_w2q[cg*3+2];
        float a2 = g_a2[cg], b2 = g_bb2[cg];
        const uint32_t* rw = y1 + c*Y1S;
        uint32_t rm[7], rc[7], rp[7];
        #pragma unroll
        for (int q=0;q<7;q++){
            rm[q] = rw[ j   *7 + q];
            rc[q] = rw[(j+1)*7 + q];
            rp[q] = rw[(j+2)*7 + q];
        }
        uint32_t pm=0, pc=0, pp=0;
        #pragma unroll
        for (int w=0; w<7; w++){
            uint32_t nm = (w<6)? rm[w+1] : 0u;
            uint32_t nc = (w<6)? rc[w+1] : 0u;
            uint32_t np = (w<6)? rp[w+1] : 0u;
            int o0 = __dp4a((int)__byte_perm(pm, rm[w], 0x6543), (int)wk0, 0)
                   + __dp4a((int)__byte_perm(pc, rc[w], 0x6543), (int)wk1, 0)
                   + __dp4a((int)__byte_perm(pp, rp[w], 0x6543), (int)wk2, 0);
            int o1 = __dp4a((int)rm[w], (int)wk0, 0)
                   + __dp4a((int)rc[w], (int)wk1, 0)
                   + __dp4a((int)rp[w], (int)wk2, 0);
            int o2 = __dp4a((int)__byte_perm(rm[w], nm, 0x4321), (int)wk0, 0)
                   + __dp4a((int)__byte_perm(rc[w], nc, 0x4321), (int)wk1, 0)
                   + __dp4a((int)__byte_perm(rp[w], np, 0x4321), (int)wk2, 0);
            int o3 = __dp4a((int)__byte_perm(rm[w], nm, 0x5432), (int)wk0, 0)
                   + __dp4a((int)__byte_perm(rc[w], nc, 0x5432), (int)wk1, 0)
                   + __dp4a((int)__byte_perm(rp[w], np, 0x5432), (int)wk2, 0);
            int outs[4] = {o0, o1, o2, o3};
            #pragma unroll
            for (int i2=0;i2<4;i2++){
                float y = clampf(fmaf(a2, (float)outs[i2], b2), 0.f, 6.f);
                int q = (int)fminf(rintf(y*inv2), 127.f);
                y2b[(j*28 + w*4 + i2)*64 + c] = (int8_t)q;
            }
            pm = rm[w]; pc = rc[w]; pp = rp[w];
        }
    }
    __syncthreads();

    uint32_t* dst = g_y2q + ((size_t)img*HWp + qtr*196)*KW3 + ch*16;
    const uint32_t* y2w = sm;
    for (int i=t; i<196*4; i+=256){
        int p = i>>2, q = i&3;
        *(uint4*)&dst[(size_t)p*KW3 + q*4] = *(const uint4*)&y2w[p*16 + q*4];
    }
}

// ---------------- conv3: persistent strips, B resident, A double-buffered ----------------
// grid (148, 2): blockIdx.y = 48-channel half; each CTA walks slabs bid, bid+148, ...
#define SB3 148
#define P3B   192                     // after 192 words of scale cache
#define P3A0  (P3B + 48*SB3)          // 192 + 7104 = 7296
#define P3A1  (P3A0 + 64*SB3)         // 7296 + 9472 = 16768
#define P3_WORDS (P3A1 + 64*SB3)      // 26240
#define P3_BYTES (P3_WORDS*4)         // 104960
#define NSLAB (NPIX/64)               // 784
__global__ __launch_bounds__(256,2) void k_conv3(const float* __restrict__ x,
                                                 float* __restrict__ out, int out_size){
    extern __shared__ __align__(16) uint32_t sm[];
    float* sa3 = (float*)sm;          // 96
    float* sb3 = (float*)(sm + 96);   // 96
    int t = threadIdx.x;
    int cb0 = blockIdx.y*48;
    uint32_t sbase = smem_u32(sm);

    if (t < 96){ sa3[t] = g_a3[t]; sb3[t] = g_bb3[t]; }
    // B half: 48 rows x 144 words, resident for all slabs
    for (int i=t; i<48*36; i+=256){
        int r = i/36, q = i%36;
        cpa16(sbase + (uint32_t)(P3B + r*SB3 + q*4)*4, &g_w3q[(cb0+r)*KW3 + q*4]);
    }
    // first A slab into buf0
    {
        const uint32_t* Ag = g_y2q + (size_t)blockIdx.x*64*KW3;
        for (int i=t; i<64*36; i+=256){
            int r = i/36, q = i%36;
            cpa16(sbase + (uint32_t)(P3A0 + r*SB3 + q*4)*4, &Ag[r*KW3 + q*4]);
        }
    }
    cp_commit_wait();
    __syncthreads();

    int lane = t & 31, warp = t >> 5, r4 = lane >> 2, w4 = lane & 3;
    int m0 = (warp & 3)*16, n0 = (warp >> 2)*24;
    uint32_t aOff = (uint32_t)(m0 + (lane&7) + ((lane>>3)&1)*8)*592 + ((lane>>4)&1)*16;
    uint32_t bBase4 = sbase + (uint32_t)P3B*4
                    + (uint32_t)(n0 + (lane&7) + ((lane>>4)&1)*8)*592 + ((lane>>3)&1)*16;
    uint32_t bBase2 = sbase + (uint32_t)P3B*4
                    + (uint32_t)(n0 + 16 + (lane&7))*592 + ((lane>>3)&1)*16;
    uint32_t abuf[2] = { sbase + (uint32_t)P3A0*4, sbase + (uint32_t)P3A1*4 };

    float s3 = g_s[3];
    float inv3 = 1.0f / s3;
    int cur = 0;
    for (int s = blockIdx.x; s < NSLAB; s += 148){
        // prefetch next slab's A into the other buffer (overlaps MMA + epilogue)
        int sn = s + 148;
        if (sn < NSLAB){
            const uint32_t* Ag = g_y2q + (size_t)sn*64*KW3;
            uint32_t dA = abuf[cur^1];
            for (int i=t; i<64*36; i+=256){
                int r = i/36, q = i%36;
                cpa16(dA + (uint32_t)(r*SB3 + q*4)*4, &Ag[r*KW3 + q*4]);
            }
        }
        asm volatile("cp.async.commit_group;");

        uint32_t aBase = abuf[cur] + aOff;
        int acc[3][4] = {};
        #pragma unroll 3
        for (int ks=0; ks<18; ks++){
            uint32_t a0,a1,a2,a3, b0,b1,b2,b3, b4,b5;
            ldm_x4(a0,a1,a2,a3, aBase + (uint32_t)ks*32);
            ldm_x4(b0,b1,b2,b3, bBase4 + (uint32_t)ks*32);
            imma(acc[0][0],acc[0][1],acc[0][2],acc[0][3], a0,a1,a2,a3, b0,b1);
            imma(acc[1][0],acc[1][1],acc[1][2],acc[1][3], a0,a1,a2,a3, b2,b3);
            ldm_x2(b4,b5, bBase2 + (uint32_t)ks*32);
            imma(acc[2][0],acc[2][1],acc[2][2],acc[2][3], a0,a1,a2,a3, b4,b5);
        }

        // direct epilogue: bias + residual + quant, 32B-sector stores
        int pA = s*64 + m0 + r4;
        int pB = pA + 8;
        int bA = pA / HWp, hwA = pA % HWp;
        int bB = pB / HWp, hwB = pB % HWp;
        size_t gA = (size_t)bA*CIN*HWp + hwA;
        size_t gB = (size_t)bB*CIN*HWp + hwB;
        #pragma unroll
        for (int ni=0; ni<3; ni++){
            int c = cb0 + n0 + ni*8 + 2*w4;
            float af0 = sa3[c], af1 = sa3[c+1];
            float bf0 = sb3[c], bf1 = sb3[c+1];
            size_t o00 = gA + (size_t)c*HWp,     o01 = gA + (size_t)(c+1)*HWp;
            size_t o10 = gB + (size_t)c*HWp,     o11 = gB + (size_t)(c+1)*HWp;
            float y0 = fmaf(af0, (float)acc[ni][0], bf0) + x[o00];
            float y1 = fmaf(af1, (float)acc[ni][1], bf1) + x[o01];
            float y2 = fmaf(af0, (float)acc[ni][2], bf0) + x[o10];
            float y3 = fmaf(af1, (float)acc[ni][3], bf1) + x[o11];
            out[o00] = clampf(rintf(y0*inv3), -127.f, 127.f) * s3;
            out[o01] = clampf(rintf(y1*inv3), -127.f, 127.f) * s3;
            out[o10] = clampf(rintf(y2*inv3), -127.f, 127.f) * s3;
            out[o11] = clampf(rintf(y3*inv3), -127.f, 127.f) * s3;
        }

        asm volatile("cp.async.wait_group 0;");
        __syncthreads();
        cur ^= 1;
    }
    if (blockIdx.x == 0 && blockIdx.y == 0){
        for (int i = OUT_ELEMS + t; i < out_size; i += 256) out[i] = g_s[3];
    }
}

// ---------------- launch ----------------
extern "C" void kernel_launch(void* const* d_in, const int* in_sizes, int n_in,
                              void* d_out, int out_size){
    const float* x  = (const float*)d_in[0];
    const float* w1 = (const float*)d_in[1];
    const float* g1 = (const float*)d_in[2];
    const float* b1 = (const float*)d_in[3];
    const float* m1 = (const float*)d_in[4];
    const float* v1 = (const float*)d_in[5];
    const float* w2 = (const float*)d_in[6];
    const float* g2 = (const float*)d_in[7];
    const float* b2 = (const float*)d_in[8];
    const float* m2 = (const float*)d_in[9];
    const float* v2 = (const float*)d_in[10];
    const float* w3 = (const float*)d_in[11];
    const float* g3 = (const float*)d_in[12];
    const float* b3 = (const float*)d_in[13];
    const float* m3 = (const float*)d_in[14];
    const float* v3 = (const float*)d_in[15];
    const float* r0 = (const float*)d_in[16];
    const float* r1 = (const float*)d_in[17];
    const float* r2 = (const float*)d_in[18];
    const float* r3 = (const float*)d_in[19];
    const int*   cl = (const int*)d_in[20];

    cudaFuncSetAttribute(k_c1dw,  cudaFuncAttributeMaxDynamicSharedMemorySize, D_BYTES);
    cudaFuncSetAttribute(k_conv3, cudaFuncAttributeMaxDynamicSharedMemorySize, P3_BYTES);

    k_prepqx<<<NPREP + NPIX/128, 192>>>(x, w1,g1,b1,m1,v1, w2,g2,b2,m2,v2,
                                        w3,g3,b3,m3,v3, r0,r1,r2,r3, cl);
    k_c1dw<<<dim3(9, NB, 4), 256, D_BYTES>>>();
    k_conv3<<<dim3(148, 2), 256, P3_BYTES>>>(x, (float*)d_out, out_size);
}

// round 16
// speedup vs baseline: 1.1451x; 1.1083x over previous
#include <cuda_runtime.h>
#include <stdint.h>

#define NB   64
#define CIN  96
#define HWp  784
#define CMID 576
#define NPIX (NB*HWp)          // 50176
#define KW1  24                // 96/4
#define KW3  144               // 576/4
#define OUT_ELEMS (NB*CIN*HWp) // 4816896

// ---------------- device scratch ----------------
__device__ float    g_s[4];
__device__ uint32_t g_xq [NPIX*KW1];
__device__ uint32_t g_y2q[NPIX*KW3];
__device__ uint32_t g_w1q[CMID*KW1];
__device__ uint32_t g_w2q[CMID*3];     // per channel: 3 row-words (k0,k1,k2,0)
__device__ uint32_t g_w3q[CIN*KW3];
__device__ float g_a1[CMID], g_bb1[CMID];
__device__ float g_a2[CMID], g_bb2[CMID];
__device__ float g_a3[CIN],  g_bb3[CIN];

__device__ __forceinline__ float clampf(float v, float lo, float hi){ return fminf(fmaxf(v,lo),hi); }

__device__ __forceinline__ void imma(int& d0,int& d1,int& d2,int& d3,
                                     uint32_t a0,uint32_t a1,uint32_t a2,uint32_t a3,
                                     uint32_t b0,uint32_t b1){
    asm volatile("mma.sync.aligned.m16n8k32.row.col.s32.s8.s8.s32 "
                 "{%0,%1,%2,%3},{%4,%5,%6,%7},{%8,%9},{%0,%1,%2,%3};"
                 : "+r"(d0),"+r"(d1),"+r"(d2),"+r"(d3)
                 : "r"(a0),"r"(a1),"r"(a2),"r"(a3),"r"(b0),"r"(b1));
}
__device__ __forceinline__ void ldm_x4(uint32_t& r0,uint32_t& r1,uint32_t& r2,uint32_t& r3,
                                       uint32_t addr){
    asm volatile("ldmatrix.sync.aligned.m8n8.x4.shared.b16 {%0,%1,%2,%3}, [%4];"
                 : "=r"(r0),"=r"(r1),"=r"(r2),"=r"(r3) : "r"(addr));
}
__device__ __forceinline__ void ldm_x2(uint32_t& r0,uint32_t& r1, uint32_t addr){
    asm volatile("ldmatrix.sync.aligned.m8n8.x2.shared.b16 {%0,%1}, [%2];"
                 : "=r"(r0),"=r"(r1) : "r"(addr));
}
__device__ __forceinline__ void cpa16(uint32_t dst, const void* src){
    asm volatile("cp.async.cg.shared.global [%0], [%1], 16;" :: "r"(dst), "l"(src));
}
__device__ __forceinline__ void cpa16z(uint32_t dst, const void* src, uint32_t nsrc){
    asm volatile("cp.async.cg.shared.global [%0], [%1], 16, %2;" :: "r"(dst), "l"(src), "r"(nsrc));
}
__device__ __forceinline__ void cp_commit_wait(){
    asm volatile("cp.async.commit_group;");
    asm volatile("cp.async.wait_group 0;");
}
__device__ __forceinline__ uint32_t smem_u32(const void* p){
    uint32_t a;
    asm("{ .reg .u64 t; cvta.to.shared.u64 t, %1; cvt.u32.u64 %0, t; }" : "=r"(a) : "l"(p));
    return a;
}

// ---------------- merged prep + qx kernel ----------------
// blocks [0,576):        conv1 weight row o=bid
// blocks [576,585):      depthwise weights, 64 ch/block
// blocks [585,681):      conv3 weight row o=bid-585
// blocks [681,681+392):  quantize-x chunk of 128 pixels (register-packed transpose)
#define NPREP (CMID + 9 + CIN)      // 681
__global__ __launch_bounds__(192) void k_prepqx(
    const float* __restrict__ x,
    const float* __restrict__ w1, const float* __restrict__ g1, const float* __restrict__ b1,
    const float* __restrict__ m1, const float* __restrict__ v1,
    const float* __restrict__ w2, const float* __restrict__ g2, const float* __restrict__ b2,
    const float* __restrict__ m2, const float* __restrict__ v2,
    const float* __restrict__ w3, const float* __restrict__ g3, const float* __restrict__ b3,
    const float* __restrict__ m3, const float* __restrict__ v3,
    const float* __restrict__ r0, const float* __restrict__ r1,
    const float* __restrict__ r2, const float* __restrict__ r3,
    const int* __restrict__ cl_)
{
    __shared__ __align__(16) uint32_t sq32[24*133 + 8];   // 12.8 KB; prep path uses first 24B as red[6]
    float* red = (float*)sq32;
    int bid = blockIdx.x, t = threadIdx.x;
    int cl = cl_[0];
    if (bid == 0 && t == 0){
        g_s[0]=r0[cl]/127.0f; g_s[1]=r1[cl]/127.0f;
        g_s[2]=r2[cl]/127.0f; g_s[3]=r3[cl]/127.0f;
    }
    if (bid < CMID){
        int o = bid;
        float sc = g1[o] * rsqrtf(v1[o] + 1e-5f);
        float wf = 0.f;
        if (t < 96) wf = w1[o*CIN + t] * sc;
        float amx = fabsf(wf);
        #pragma unroll
        for (int off=16; off; off>>=1) amx = fmaxf(amx, __shfl_xor_sync(0xffffffffu, amx, off));
        if ((t & 31) == 0) red[t>>5] = amx;
        __syncthreads();
        float mx = red[0];
        #pragma unroll
        for (int i=1;i<6;i++) mx = fmaxf(mx, red[i]);
        float sw = mx / 127.0f;
        if (t < 96){
            float q = clampf(rintf(wf / sw), -127.f, 127.f);
            ((int8_t*)g_w1q)[o*CIN + t] = (int8_t)q;
        }
        if (t == 0){
            float s0 = r0[cl]/127.0f;
            g_a1[o] = s0*sw; g_bb1[o] = b1[o] - m1[o]*sc;
        }
    } else if (bid < CMID + 9){
        if (t < 64){
            int c = (bid - CMID)*64 + t;
            float sc = g2[c] * rsqrtf(v2[c] + 1e-5f);
            float wf[9]; float mx = 0.f;
            #pragma unroll
            for (int j=0;j<9;j++){ wf[j] = w2[c*9+j]*sc; mx = fmaxf(mx, fabsf(wf[j])); }
            float sw = mx / 127.0f;
            #pragma unroll
            for (int dh=0; dh<3; dh++){
                uint32_t pk = 0;
                #pragma unroll
                for (int dw=0; dw<3; dw++){
                    int q = (int)clampf(rintf(wf[dh*3+dw]/sw), -127.f, 127.f);
                    pk |= ((uint32_t)(uint8_t)(int8_t)q) << (8*dw);
                }
                g_w2q[c*3 + dh] = pk;
            }
            float s1 = r1[cl]/127.0f;
            g_a2[c] = s1*sw; g_bb2[c] = b2[c] - m2[c]*sc;
        }
    } else if (bid < NPREP){
        int o = bid - (CMID + 9);
        float sc = g3[o] * rsqrtf(v3[o] + 1e-5f);
        float f0 = w3[o*CMID + t      ]*sc;
        float f1 = w3[o*CMID + t + 192]*sc;
        float f2 = w3[o*CMID + t + 384]*sc;
        float amx = fmaxf(fabsf(f0), fmaxf(fabsf(f1), fabsf(f2)));
        #pragma unroll
        for (int off=16; off; off>>=1) amx = fmaxf(amx, __shfl_xor_sync(0xffffffffu, amx, off));
        if ((t & 31) == 0) red[t>>5] = amx;
        __syncthreads();
        float mx = red[0];
        #pragma unroll
        for (int i=1;i<6;i++) mx = fmaxf(mx, red[i]);
        float sw = mx / 127.0f;
        int8_t* dst = (int8_t*)g_w3q + o*CMID;
        dst[t      ] = (int8_t)clampf(rintf(f0/sw), -127.f, 127.f);
        dst[t + 192] = (int8_t)clampf(rintf(f1/sw), -127.f, 127.f);
        dst[t + 384] = (int8_t)clampf(rintf(f2/sw), -127.f, 127.f);
        if (t == 0){
            float s2 = r2[cl]/127.0f;
            g_a3[o] = s2*sw; g_bb3[o] = b3[o] - m3[o]*sc;
        }
    } else {
        // quantize-x: register-packed transpose. 128 px/block, word = 4ch x 1px.
        int p0 = (bid - NPREP)*128;
        float s0 = r0[cl]/127.0f;
        float inv0 = 1.0f/s0;
        #pragma unroll 4
        for (int i=0;i<16;i++){
            int w = t + 192*i;             // 0..3071
            int pl = w & 127, kw = w >> 7; // pl = pixel lane, kw = channel word
            int p = p0 + pl;
            int b = p / HWp, hw = p % HWp;
            const float* xb = x + (size_t)b*CIN*HWp + (size_t)(kw*4)*HWp + hw;
            int q0 = __float2int_rn(clampf(xb[0      ]*inv0, -127.f, 127.f));
            int q1 = __float2int_rn(clampf(xb[HWp    ]*inv0, -127.f, 127.f));
            int q2 = __float2int_rn(clampf(xb[2*HWp  ]*inv0, -127.f, 127.f));
            int q3 = __float2int_rn(clampf(xb[3*HWp  ]*inv0, -127.f, 127.f));
            uint32_t pk = (uint32_t)(q0 & 0xff)
                        | ((uint32_t)(q1 & 0xff) << 8)
                        | ((uint32_t)(q2 & 0xff) << 16)
                        | ((uint32_t)(q3 & 0xff) << 24);
            sq32[kw*133 + pl] = pk;
        }
        __syncthreads();
        uint32_t* ow = g_xq + (size_t)p0*KW1;
        #pragma unroll 4
        for (int i=0;i<16;i++){
            int w = t + 192*i;
            int pl = w / 24, kw = w % 24;
            ow[w] = sq32[kw*133 + pl];
        }
    }
}

// ---------------- fused conv1 + depthwise, quarter-image slabs, 3 CTA/SM ----------------
#define SAW  28            // A/W smem pitch (words) = 112 B
#define SPX  256           // padded slab px (252 data)
#define Y1S  65            // y1 per-channel stride (words); 63 data words
#define D_OFF_W  (SPX*SAW)                 // 7168
#define D_OFF_Y1 (D_OFF_W + 64*SAW)        // 8960
#define D_OFF_SC (D_OFF_Y1 + 64*Y1S)       // 13120
#define D_WORDS  (D_OFF_SC + 128)          // 13248
#define D_BYTES  (D_WORDS*4)               // 52992
__global__ __launch_bounds__(256,3) void k_c1dw(){
    extern __shared__ __align__(16) uint32_t sm[];
    uint32_t* y1 = sm + D_OFF_Y1;
    float* sAf = (float*)(sm + D_OFF_SC);
    float* sBf = (float*)(sm + D_OFF_SC + 64);
    int t    = threadIdx.x;
    int ch   = blockIdx.x;
    int img  = blockIdx.y;
    int qtr  = blockIdx.z;
    int off  = qtr*196 - 28;       // slab px -> image px offset
    uint32_t sbase = smem_u32(sm);

    if (t < 64){ sAf[t] = g_a1[ch*64+t]; sBf[t] = g_bb1[ch*64+t]; }
    const uint32_t* Aim = g_xq + (size_t)img*HWp*KW1;
    for (int i=t; i<SPX*6; i+=256){
        int sp = i/6, q = i%6;
        int ip = sp + off;
        uint32_t v = (sp < 252 && (unsigned)ip < (unsigned)HWp) ? 16u : 0u;
        cpa16z(sbase + (uint32_t)(sp*SAW + q*4)*4, &Aim[(v? ip:0)*KW1 + q*4], v);
    }
    for (int i=t; i<64*6; i+=256){
        int r = i/6, q = i%6;
        cpa16(sbase + (uint32_t)(D_OFF_W + r*SAW + q*4)*4, &g_w1q[(ch*64+r)*KW1 + q*4]);
    }
    cp_commit_wait();
    __syncthreads();

    int lane = t & 31, warp = t >> 5, r4 = lane >> 2, w4 = lane & 3;
    float inv1 = 1.0f / g_s[1];
    int8_t* y1b = (int8_t*)y1;
    uint32_t aLane = sbase + ((lane&7) + ((lane>>3)&1)*8)*112 + ((lane>>4)&1)*16;
    uint32_t bLane = sbase + (uint32_t)D_OFF_W*4
                   + ((lane&7) + ((lane>>4)&1)*8)*112 + ((lane>>3)&1)*16;

    #pragma unroll
    for (int tile = warp; tile < 16; tile += 8){
        int m0 = tile*16;
        int acc[8][4] = {};
        #pragma unroll
        for (int kc=0;kc<3;kc++){
            uint32_t a0,a1,a2,a3;
            ldm_x4(a0,a1,a2,a3, aLane + (uint32_t)(m0*112 + kc*32));
            #pragma unroll
            for (int tp=0; tp<4; tp++){
                uint32_t b0,b1,b2,b3;
                ldm_x4(b0,b1,b2,b3, bLane + (uint32_t)(tp*16*112 + kc*32));
                imma(acc[2*tp  ][0],acc[2*tp  ][1],acc[2*tp  ][2],acc[2*tp  ][3],
                     a0,a1,a2,a3, b0,b1);
                imma(acc[2*tp+1][0],acc[2*tp+1][1],acc[2*tp+1][2],acc[2*tp+1][3],
                     a0,a1,a2,a3, b2,b3);
            }
        }
        int px0 = m0 + r4, px1 = px0 + 8;
        bool s0ok = px0 < 252, s1ok = px1 < 252;
        bool v0 = s0ok && (unsigned)(px0 + off) < (unsigned)HWp;
        bool v1 = s1ok && (unsigned)(px1 + off) < (unsigned)HWp;
        #pragma unroll
        for (int ni=0;ni<8;ni++){
            int c0 = ni*8 + 2*w4;
            float af0 = sAf[c0], af1 = sAf[c0+1];
            float bb0 = sBf[c0], bb1 = sBf[c0+1];
            float q0 = fminf(rintf(clampf(fmaf(af0,(float)acc[ni][0],bb0),0.f,6.f)*inv1),127.f);
            float q1 = fminf(rintf(clampf(fmaf(af1,(float)acc[ni][1],bb1),0.f,6.f)*inv1),127.f);
            float q2 = fminf(rintf(clampf(fmaf(af0,(float)acc[ni][2],bb0),0.f,6.f)*inv1),127.f);
            float q3 = fminf(rintf(clampf(fmaf(af1,(float)acc[ni][3],bb1),0.f,6.f)*inv1),127.f);
            if (s0ok){
                y1b[ c0   *260 + px0] = v0 ? (int8_t)(int)q0 : (int8_t)0;
                y1b[(c0+1)*260 + px0] = v0 ? (int8_t)(int)q1 : (int8_t)0;
            }
            if (s1ok){
                y1b[ c0   *260 + px1] = v1 ? (int8_t)(int)q2 : (int8_t)0;
                y1b[(c0+1)*260 + px1] = v1 ? (int8_t)(int)q3 : (int8_t)0;
            }
        }
    }
    __syncthreads();

    // depthwise: output rows j=0..6 use y1 slab rows j, j+1, j+2
    float inv2 = 1.0f / g_s[2];
    int8_t* y2b = (int8_t*)sm;     // alias over A region (free after MMA)
    for (int task=t; task<64*7; task+=256){
        int c = task & 63, j = task >> 6;
        int cg = ch*64 + c;
        uint32_t wk0 = g_w2q[cg*3+0], wk1 = g_w2q[cg*3+1], wk2 = g_w2q[cg*3+2];
        float a2 = g_a2[cg], b2 = g_bb2[cg];
        const uint32_t* rw = y1 + c*Y1S;
        uint32_t rm[7], rc[7], rp[7];
        #pragma unroll
        for (int q=0;q<7;q++){
            rm[q] = rw[ j   *7 + q];
            rc[q] = rw[(j+1)*7 + q];
            rp[q] = rw[(j+2)*7 + q];
        }
        uint32_t pm=0, pc=0, pp=0;
        #pragma unroll
        for (int w=0; w<7; w++){
            uint32_t nm = (w<6)? rm[w+1] : 0u;
            uint32_t nc = (w<6)? rc[w+1] : 0u;
            uint32_t np = (w<6)? rp[w+1] : 0u;
            int o0 = __dp4a((int)__byte_perm(pm, rm[w], 0x6543), (int)wk0, 0)
                   + __dp4a((int)__byte_perm(pc, rc[w], 0x6543), (int)wk1, 0)
                   + __dp4a((int)__byte_perm(pp, rp[w], 0x6543), (int)wk2, 0);
            int o1 = __dp4a((int)rm[w], (int)wk0, 0)
                   + __dp4a((int)rc[w], (int)wk1, 0)
                   + __dp4a((int)rp[w], (int)wk2, 0);
            int o2 = __dp4a((int)__byte_perm(rm[w], nm, 0x4321), (int)wk0, 0)
                   + __dp4a((int)__byte_perm(rc[w], nc, 0x4321), (int)wk1, 0)
                   + __dp4a((int)__byte_perm(rp[w], np, 0x4321), (int)wk2, 0);
            int o3 = __dp4a((int)__byte_perm(rm[w], nm, 0x5432), (int)wk0, 0)
                   + __dp4a((int)__byte_perm(rc[w], nc, 0x5432), (int)wk1, 0)
                   + __dp4a((int)__byte_perm(rp[w], np, 0x5432), (int)wk2, 0);
            int outs[4] = {o0, o1, o2, o3};
            #pragma unroll
            for (int i2=0;i2<4;i2++){
                float y = clampf(fmaf(a2, (float)outs[i2], b2), 0.f, 6.f);
                int q = (int)fminf(rintf(y*inv2), 127.f);
                y2b[(j*28 + w*4 + i2)*64 + c] = (int8_t)q;
            }
            pm = rm[w]; pc = rc[w]; pp = rp[w];
        }
    }
    __syncthreads();

    uint32_t* dst = g_y2q + ((size_t)img*HWp + qtr*196)*KW3 + ch*16;
    const uint32_t* y2w = sm;
    for (int i=t; i<196*4; i+=256){
        int p = i>>2, q = i&3;
        *(uint4*)&dst[(size_t)p*KW3 + q*4] = *(const uint4*)&y2w[p*16 + q*4];
    }
}

// ---------------- conv3: persistent strips, B resident, A double-buffered ----------------
#define SB3 148
#define P3B   192                     // after 192 words of scale cache
#define P3A0  (P3B + 48*SB3)          // 192 + 7104 = 7296
#define P3A1  (P3A0 + 64*SB3)         // 7296 + 9472 = 16768
#define P3_WORDS (P3A1 + 64*SB3)      // 26240
#define P3_BYTES (P3_WORDS*4)         // 104960
#define NSLAB (NPIX/64)               // 784
__global__ __launch_bounds__(256,2) void k_conv3(const float* __restrict__ x,
                                                 float* __restrict__ out, int out_size){
    extern __shared__ __align__(16) uint32_t sm[];
    float* sa3 = (float*)sm;          // 96
    float* sb3 = (float*)(sm + 96);   // 96
    int t = threadIdx.x;
    int cb0 = blockIdx.y*48;
    uint32_t sbase = smem_u32(sm);

    if (t < 96){ sa3[t] = g_a3[t]; sb3[t] = g_bb3[t]; }
    for (int i=t; i<48*36; i+=256){
        int r = i/36, q = i%36;
        cpa16(sbase + (uint32_t)(P3B + r*SB3 + q*4)*4, &g_w3q[(cb0+r)*KW3 + q*4]);
    }
    {
        const uint32_t* Ag = g_y2q + (size_t)blockIdx.x*64*KW3;
        for (int i=t; i<64*36; i+=256){
            int r = i/36, q = i%36;
            cpa16(sbase + (uint32_t)(P3A0 + r*SB3 + q*4)*4, &Ag[r*KW3 + q*4]);
        }
    }
    cp_commit_wait();
    __syncthreads();

    int lane = t & 31, warp = t >> 5, r4 = lane >> 2, w4 = lane & 3;
    int m0 = (warp & 3)*16, n0 = (warp >> 2)*24;
    uint32_t aOff = (uint32_t)(m0 + (lane&7) + ((lane>>3)&1)*8)*592 + ((lane>>4)&1)*16;
    uint32_t bBase4 = sbase + (uint32_t)P3B*4
                    + (uint32_t)(n0 + (lane&7) + ((lane>>4)&1)*8)*592 + ((lane>>3)&1)*16;
    uint32_t bBase2 = sbase + (uint32_t)P3B*4
                    + (uint32_t)(n0 + 16 + (lane&7))*592 + ((lane>>3)&1)*16;
    uint32_t abuf[2] = { sbase + (uint32_t)P3A0*4, sbase + (uint32_t)P3A1*4 };

    float s3 = g_s[3];
    float inv3 = 1.0f / s3;
    int cur = 0;
    for (int s = blockIdx.x; s < NSLAB; s += 148){
        int sn = s + 148;
        if (sn < NSLAB){
            const uint32_t* Ag = g_y2q + (size_t)sn*64*KW3;
            uint32_t dA = abuf[cur^1];
            for (int i=t; i<64*36; i+=256){
                int r = i/36, q = i%36;
                cpa16(dA + (uint32_t)(r*SB3 + q*4)*4, &Ag[r*KW3 + q*4]);
            }
        }
        asm volatile("cp.async.commit_group;");

        uint32_t aBase = abuf[cur] + aOff;
        int acc[3][4] = {};
        #pragma unroll 3
        for (int ks=0; ks<18; ks++){
            uint32_t a0,a1,a2,a3, b0,b1,b2,b3, b4,b5;
            ldm_x4(a0,a1,a2,a3, aBase + (uint32_t)ks*32);
            ldm_x4(b0,b1,b2,b3, bBase4 + (uint32_t)ks*32);
            imma(acc[0][0],acc[0][1],acc[0][2],acc[0][3], a0,a1,a2,a3, b0,b1);
            imma(acc[1][0],acc[1][1],acc[1][2],acc[1][3], a0,a1,a2,a3, b2,b3);
            ldm_x2(b4,b5, bBase2 + (uint32_t)ks*32);
            imma(acc[2][0],acc[2][1],acc[2][2],acc[2][3], a0,a1,a2,a3, b4,b5);
        }

        int pA = s*64 + m0 + r4;
        int pB = pA + 8;
        int bA = pA / HWp, hwA = pA % HWp;
        int bB = pB / HWp, hwB = pB % HWp;
        size_t gA = (size_t)bA*CIN*HWp + hwA;
        size_t gB = (size_t)bB*CIN*HWp + hwB;
        #pragma unroll
        for (int ni=0; ni<3; ni++){
            int c = cb0 + n0 + ni*8 + 2*w4;
            float af0 = sa3[c], af1 = sa3[c+1];
            float bf0 = sb3[c], bf1 = sb3[c+1];
            size_t o00 = gA + (size_t)c*HWp,     o01 = gA + (size_t)(c+1)*HWp;
            size_t o10 = gB + (size_t)c*HWp,     o11 = gB + (size_t)(c+1)*HWp;
            float y0 = fmaf(af0, (float)acc[ni][0], bf0) + x[o00];
            float y1 = fmaf(af1, (float)acc[ni][1], bf1) + x[o01];
            float y2 = fmaf(af0, (float)acc[ni][2], bf0) + x[o10];
            float y3 = fmaf(af1, (float)acc[ni][3], bf1) + x[o11];
            out[o00] = clampf(rintf(y0*inv3), -127.f, 127.f) * s3;
            out[o01] = clampf(rintf(y1*inv3), -127.f, 127.f) * s3;
            out[o10] = clampf(rintf(y2*inv3), -127.f, 127.f) * s3;
            out[o11] = clampf(rintf(y3*inv3), -127.f, 127.f) * s3;
        }

        asm volatile("cp.async.wait_group 0;");
        __syncthreads();
        cur ^= 1;
    }
    if (blockIdx.x == 0 && blockIdx.y == 0){
        for (int i = OUT_ELEMS + t; i < out_size; i += 256) out[i] = g_s[3];
    }
}

// ---------------- launch ----------------
extern "C" void kernel_launch(void* const* d_in, const int* in_sizes, int n_in,
                              void* d_out, int out_size){
    const float* x  = (const float*)d_in[0];
    const float* w1 = (const float*)d_in[1];
    const float* g1 = (const float*)d_in[2];
    const float* b1 = (const float*)d_in[3];
    const float* m1 = (const float*)d_in[4];
    const float* v1 = (const float*)d_in[5];
    const float* w2 = (const float*)d_in[6];
    const float* g2 = (const float*)d_in[7];
    const float* b2 = (const float*)d_in[8];
    const float* m2 = (const float*)d_in[9];
    const float* v2 = (const float*)d_in[10];
    const float* w3 = (const float*)d_in[11];
    const float* g3 = (const float*)d_in[12];
    const float* b3 = (const float*)d_in[13];
    const float* m3 = (const float*)d_in[14];
    const float* v3 = (const float*)d_in[15];
    const float* r0 = (const float*)d_in[16];
    const float* r1 = (const float*)d_in[17];
    const float* r2 = (const float*)d_in[18];
    const float* r3 = (const float*)d_in[19];
    const int*   cl = (const int*)d_in[20];

    cudaFuncSetAttribute(k_c1dw,  cudaFuncAttributeMaxDynamicSharedMemorySize, D_BYTES);
    cudaFuncSetAttribute(k_conv3, cudaFuncAttributeMaxDynamicSharedMemorySize, P3_BYTES);

    k_prepqx<<<NPREP + NPIX/128, 192>>>(x, w1,g1,b1,m1,v1, w2,g2,b2,m2,v2,
                                        w3,g3,b3,m3,v3, r0,r1,r2,r3, cl);
    k_c1dw<<<dim3(9, NB, 4), 256, D_BYTES>>>();
    k_conv3<<<dim3(148, 2), 256, P3_BYTES>>>(x, (float*)d_out, out_size);
}